// round 15
// baseline (speedup 1.0000x reference)
#include <cuda_runtime.h>
#include <cuda_bf16.h>
#include <cstdint>

#define BB 8
#define CC 64
#define HH 128
#define WW 128
#define HWP (HH*WW)
#define K2 9
#define OFFC 18
#define MASKC 9
#define NOUT 27

// ---------------------------------------------------------------------------
// Device scratch (graph-safe)
// ---------------------------------------------------------------------------
__device__ float g_offset[BB * OFFC * HWP];
__device__ float g_mask  [BB * MASKC * HWP];
__device__ float g_xt    [(size_t)BB * HWP * CC];   // x in NHWC (33.5 MB)
// deform W fragments: [tap][hi/lo][nn(8)][kk(4)][lane(32)] x uint2
__device__ __align__(16) uint2 g_wfrag[K2 * 2 * 8 * 4 * 32];
// offset/mask W fragments (N padded 27->32): [tap][hi/lo][nn(4)][kk(4)][lane(32)]
__device__ __align__(16) uint2 g_ofrag[K2 * 2 * 4 * 4 * 32];

__device__ __forceinline__ uint32_t smem_u32(const void* p) {
    uint32_t a;
    asm("{ .reg .u64 t; cvta.to.shared.u64 t, %1; cvt.u32.u64 %0, t; }" : "=r"(a) : "l"(p));
    return a;
}

__device__ __forceinline__ void ldm_x4(uint32_t* r, uint32_t addr) {
    asm volatile("ldmatrix.sync.aligned.m8n8.x4.shared.b16 {%0,%1,%2,%3}, [%4];"
        : "=r"(r[0]), "=r"(r[1]), "=r"(r[2]), "=r"(r[3]) : "r"(addr));
}

__device__ __forceinline__ void mma16816(float* d, const uint32_t* a, const uint32_t* b) {
    asm volatile(
        "mma.sync.aligned.m16n8k16.row.col.f32.bf16.bf16.f32 "
        "{%0,%1,%2,%3}, {%4,%5,%6,%7}, {%8,%9}, {%0,%1,%2,%3};"
        : "+f"(d[0]), "+f"(d[1]), "+f"(d[2]), "+f"(d[3])
        : "r"(a[0]), "r"(a[1]), "r"(a[2]), "r"(a[3]), "r"(b[0]), "r"(b[1]));
}

__device__ __forceinline__ void split_pack(float s0, float s1,
                                           uint32_t& hp, uint32_t& lp) {
    __nv_bfloat16 h0 = __float2bfloat16(s0);
    __nv_bfloat16 h1 = __float2bfloat16(s1);
    __nv_bfloat16 l0 = __float2bfloat16(s0 - __bfloat162float(h0));
    __nv_bfloat16 l1 = __float2bfloat16(s1 - __bfloat162float(h1));
    hp = (uint32_t)__bfloat16_as_ushort(h0) | ((uint32_t)__bfloat16_as_ushort(h1) << 16);
    lp = (uint32_t)__bfloat16_as_ushort(l0) | ((uint32_t)__bfloat16_as_ushort(l1) << 16);
}

#define CP_ASYNC16(dst, src) \
    asm volatile("cp.async.cg.shared.global [%0], [%1], 16;" :: "r"(dst), "l"(src) : "memory")
#define CP_COMMIT() asm volatile("cp.async.commit_group;" ::: "memory")
#define CP_WAIT0()  asm volatile("cp.async.wait_group 0;" ::: "memory")

// ---------------------------------------------------------------------------
// NCHW -> NHWC transpose via smem tiles
// ---------------------------------------------------------------------------
__global__ __launch_bounds__(256) void nhwc_kernel(const float* __restrict__ x)
{
    __shared__ float tile[32][33];
    const int b  = blockIdx.z;
    const int c0 = blockIdx.y * 32;
    const int p0 = blockIdx.x * 32;
    const int tx = threadIdx.x, ty = threadIdx.y;

#pragma unroll
    for (int i = 0; i < 4; i++)
        tile[ty + 8 * i][tx] = x[((size_t)b * CC + c0 + ty + 8 * i) * HWP + p0 + tx];
    __syncthreads();
#pragma unroll
    for (int i = 0; i < 4; i++)
        g_xt[((size_t)b * HWP + p0 + ty + 8 * i) * CC + c0 + tx] = tile[tx][ty + 8 * i];
}

// ---------------------------------------------------------------------------
// Setup: w_conv fragments (deform)
// ---------------------------------------------------------------------------
__global__ void wfrag_kernel(const float* __restrict__ w_conv)
{
    int i = blockIdx.x * 256 + threadIdx.x;
    if (i >= K2 * 2 * 8 * 4 * 32) return;
    int lane = i & 31;
    int kk   = (i >> 5) & 3;
    int nn   = (i >> 7) & 7;
    int hl   = (i >> 10) & 1;
    int k    = i >> 11;

    int co    = nn * 8 + (lane >> 2);
    int cbase = kk * 16 + 2 * (lane & 3);

    uint32_t regs[2];
#pragma unroll
    for (int r = 0; r < 2; r++) {
        uint32_t pk = 0;
#pragma unroll
        for (int j = 0; j < 2; j++) {
            int c = cbase + r * 8 + j;
            float wv = w_conv[(co * CC + c) * K2 + k];
            __nv_bfloat16 hi = __float2bfloat16(wv);
            float lov = wv - __bfloat162float(hi);
            __nv_bfloat16 v = hl ? __float2bfloat16(lov) : hi;
            pk |= ((uint32_t)__bfloat16_as_ushort(v)) << (16 * j);
        }
        regs[r] = pk;
    }
    g_wfrag[i] = make_uint2(regs[0], regs[1]);
}

// ---------------------------------------------------------------------------
// Setup: offset+mask weight fragments, N padded to 32 (rows 27..31 zero)
// ---------------------------------------------------------------------------
__global__ void ofrag_kernel(const float* __restrict__ w_off,
                             const float* __restrict__ w_msk)
{
    int i = blockIdx.x * 256 + threadIdx.x;
    if (i >= K2 * 2 * 4 * 4 * 32) return;
    int lane = i & 31;
    int kk   = (i >> 5) & 3;
    int nn   = (i >> 7) & 3;
    int hl   = (i >> 9) & 1;
    int k    = i >> 10;

    int co    = nn * 8 + (lane >> 2);
    int cbase = kk * 16 + 2 * (lane & 3);

    uint32_t regs[2];
#pragma unroll
    for (int r = 0; r < 2; r++) {
        uint32_t pk = 0;
#pragma unroll
        for (int j = 0; j < 2; j++) {
            int c = cbase + r * 8 + j;
            float wv = 0.f;
            if (co < OFFC)      wv = w_off[(co * CC + c) * K2 + k];
            else if (co < NOUT) wv = w_msk[((co - OFFC) * CC + c) * K2 + k];
            __nv_bfloat16 hi = __float2bfloat16(wv);
            float lov = wv - __bfloat162float(hi);
            __nv_bfloat16 v = hl ? __float2bfloat16(lov) : hi;
            pk |= ((uint32_t)__bfloat16_as_ushort(v)) << (16 * j);
        }
        regs[r] = pk;
    }
    g_ofrag[i] = make_uint2(regs[0], regs[1]);
}

// ---------------------------------------------------------------------------
// Kernel 1: offset/mask conv via mma.sync (round-14 version, proven 77.2 us)
// ---------------------------------------------------------------------------
#define OM_WBYTES (2 * 34 * 128)             // hi+lo window per warp (8704 B)
#define OM_SMEM   (4 * OM_WBYTES + 1024)

__global__ __launch_bounds__(128) void offmask_kernel()
{
    extern __shared__ char smraw[];
    const uint32_t raw_u  = smem_u32(smraw);
    const uint32_t base_u = (raw_u + 1023) & ~1023u;
    char* const smb = smraw + (base_u - raw_u);

    const int t    = threadIdx.x;
    const int lane = t & 31;
    const int wrp  = t >> 5;
    const int h    = blockIdx.x;
    const int b    = blockIdx.y;

    char* const wt_hi = smb + wrp * OM_WBYTES;
    char* const wt_lo = wt_hi + 34 * 128;
    const uint32_t uHi = base_u + wrp * OM_WBYTES;
    const uint32_t uLo = uHi + 34 * 128;

    float acc[32];
#pragma unroll
    for (int i = 0; i < 32; i++) acc[i] = 0.f;

    const float* xb = g_xt + (size_t)b * HWP * CC;
    const uint32_t lane_chunk = lane >> 2;
    const uint32_t lane_rem   = (lane & 3) << 2;
    const int p0 = wrp * 32 - 1;

#pragma unroll 1
    for (int ki = 0; ki < 3; ki++) {
        const int yy = h + ki - 1;
        const bool yok = (yy >= 0) && (yy < HH);

        __syncwarp();
#pragma unroll 2
        for (int pi = 0; pi < 34; pi++) {
            const int q = p0 + pi;
            float2 a = make_float2(0.f, 0.f);
            if (yok && q >= 0 && q < WW)
                a = *(const float2*)(xb + (size_t)(yy * WW + q) * CC + 2 * lane);
            uint32_t hp, lp;
            split_pack(a.x, a.y, hp, lp);
            uint32_t so = (uint32_t)(pi * 128)
                        + (((lane_chunk ^ (uint32_t)(pi & 7)) << 4) | lane_rem);
            *(uint32_t*)(wt_hi + so) = hp;
            *(uint32_t*)(wt_lo + so) = lp;
        }
        __syncwarp();

#pragma unroll 1
        for (int kj = 0; kj < 3; kj++) {
            const int k = ki * 3 + kj;
            const uint2* wfb = g_ofrag + (size_t)k * 1024 + lane;

            uint32_t afrh[2][4][4], afrl[2][4][4];
#pragma unroll
            for (int mt = 0; mt < 2; mt++) {
                const int rs = mt * 16 + (lane & 15) + kj;
                const uint32_t rb = (uint32_t)(rs * 128);
                const uint32_t r7 = (uint32_t)(rs & 7);
#pragma unroll
                for (int kk = 0; kk < 4; kk++) {
                    uint32_t chunk = (uint32_t)(kk * 2) + (uint32_t)(lane >> 4);
                    ldm_x4(afrh[mt][kk], uHi + rb + ((chunk ^ r7) << 4));
                    ldm_x4(afrl[mt][kk], uLo + rb + ((chunk ^ r7) << 4));
                }
            }

#pragma unroll
            for (int kk = 0; kk < 4; kk++) {
                uint2 bh[4];
#pragma unroll
                for (int j = 0; j < 4; j++)
                    bh[j] = __ldg(wfb + j * 128 + kk * 32);
#pragma unroll
                for (int j = 0; j < 4; j++) {
                    mma16816(acc + (0 * 4 + j) * 4, afrh[0][kk], &bh[j].x);
                    mma16816(acc + (1 * 4 + j) * 4, afrh[1][kk], &bh[j].x);
                }
#pragma unroll
                for (int j = 0; j < 4; j++) {
                    mma16816(acc + (0 * 4 + j) * 4, afrl[0][kk], &bh[j].x);
                    mma16816(acc + (1 * 4 + j) * 4, afrl[1][kk], &bh[j].x);
                }
                uint2 bl[4];
#pragma unroll
                for (int j = 0; j < 4; j++)
                    bl[j] = __ldg(wfb + 512 + j * 128 + kk * 32);
#pragma unroll
                for (int j = 0; j < 4; j++) {
                    mma16816(acc + (0 * 4 + j) * 4, afrh[0][kk], &bl[j].x);
                    mma16816(acc + (1 * 4 + j) * 4, afrh[1][kk], &bl[j].x);
                }
            }
        }
    }

#pragma unroll
    for (int mt = 0; mt < 2; mt++) {
        int m = wrp * 32 + mt * 16 + (lane >> 2);
#pragma unroll
        for (int nn = 0; nn < 4; nn++) {
            int n = nn * 8 + 2 * (lane & 3);
            const float* a = acc + (mt * 4 + nn) * 4;
#pragma unroll
            for (int q = 0; q < 4; q++) {
                int ch = n + (q & 1);
                int mm = m + (q >> 1) * 8;
                float v = a[q];
                int pix = h * WW + mm;
                if (ch < OFFC)
                    g_offset[(b * OFFC + ch) * HWP + pix] = v;
                else if (ch < NOUT)
                    g_mask[(b * MASKC + ch - OFFC) * HWP + pix] =
                        1.f / (1.f + __expf(-v));
            }
        }
    }
}

// ---------------------------------------------------------------------------
// Kernel 2: deform — 256 threads / 8 warps, cp.async double-buffered W,
// B-reuse mma, WARP-PRIVATE params (one __syncthreads per tap total).
// ---------------------------------------------------------------------------
#define SM_WF0     32768
#define SM_WF1     49152
#define SM_IDX_OFF 65536
#define SM_WT_OFF  (65536 + 2048)
#define SMEM_BYTES (65536 + 4096 + 1024)

__global__ __launch_bounds__(256, 3) void deform_kernel(float* __restrict__ out)
{
    extern __shared__ char smraw[];
    const uint32_t raw_u  = smem_u32(smraw);
    const uint32_t base_u = (raw_u + 1023) & ~1023u;
    char* const smb = smraw + (base_u - raw_u);

    const uint32_t uAhi = base_u;            // 16 KB hi A-tile [128px][64c]
    const uint32_t uAlo = base_u + 16384;    // 16 KB lo A-tile
    int4*   const sIdx = (int4*)(smb + SM_IDX_OFF);
    float4* const sWt  = (float4*)(smb + SM_WT_OFF);

    const int t    = threadIdx.x;
    const int lane = t & 31;
    const int wrp  = t >> 5;
    const int h    = blockIdx.x;
    const int b    = blockIdx.y;

    float acc[32];
#pragma unroll
    for (int i = 0; i < 32; i++) acc[i] = 0.f;

    const float* xb = g_xt + (size_t)b * HWP * CC;

    uint32_t lda[4];
    {
        const int r = wrp * 16 + (lane & 15);
#pragma unroll
        for (int kk = 0; kk < 4; kk++) {
            int chunk = kk * 2 + (lane >> 4);
            lda[kk] = (uint32_t)(r * 128 + ((chunk ^ (r & 7)) * 16));
        }
    }
    const uint32_t lane_chunk = lane >> 2;
    const uint32_t lane_rem   = (lane & 3) << 2;

    // warp-private param pixel: lanes 0-15 own pixels wrp*16+lane (16-31 mirror)
    const int pixW = wrp * 16 + (lane & 15);
    const int pixT = h * WW + pixW;
    float p_offy = g_offset[(b * OFFC + 0) * HWP + pixT];
    float p_offx = g_offset[(b * OFFC + 1) * HWP + pixT];
    float p_msk  = g_mask  [(b * MASKC + 0) * HWP + pixT];

    // pre-loop: async-stage W(0) into buffer 0
    {
        const char* src = (const char*)(g_wfrag) + 0;
#pragma unroll
        for (int i = 0; i < 4; i++)
            CP_ASYNC16(base_u + SM_WF0 + (t + 256 * i) * 16,
                       src + (t + 256 * i) * 16);
        CP_COMMIT();
    }

#pragma unroll 1
    for (int k = 0; k < K2; k++) {
        CP_WAIT0();
        __syncthreads();   // W(k) landed; all warps done reading the other buffer

        const uint32_t wfOff = (k & 1) ? SM_WF1 : SM_WF0;

        // ---- async-stage W(k+1) into the other buffer (hides under mma) ----
        if (k + 1 < K2) {
            const char* src = (const char*)(g_wfrag + (size_t)(k + 1) * 2048);
            const uint32_t dst = base_u + (((k + 1) & 1) ? SM_WF1 : SM_WF0);
#pragma unroll
            for (int i = 0; i < 4; i++)
                CP_ASYNC16(dst + (t + 256 * i) * 16, src + (t + 256 * i) * 16);
            CP_COMMIT();
        }

        // ---- bilinear params, WARP-PRIVATE (lane<16 writes own pixel) ----
        {
            const int ki = k / 3, kj = k % 3;
            float py = (float)(h + ki - 1) + p_offy;
            float px = (float)(pixW + kj - 1) + p_offx;
            float y0f = floorf(py), x0f = floorf(px);
            int   y0 = (int)y0f,    x0 = (int)x0f;
            int   y1 = y0 + 1,      x1 = x0 + 1;
            float wy1 = py - y0f,   wx1 = px - x0f;
            float wy0 = 1.f - wy1,  wx0 = 1.f - wx1;

            bool vy0 = (y0 >= 0) && (y0 < HH), vy1 = (y1 >= 0) && (y1 < HH);
            bool vx0 = (x0 >= 0) && (x0 < WW), vx1 = (x1 >= 0) && (x1 < WW);

            float w00 = (vy0 && vx0) ? wy0 * wx0 * p_msk : 0.f;
            float w01 = (vy0 && vx1) ? wy0 * wx1 * p_msk : 0.f;
            float w10 = (vy1 && vx0) ? wy1 * wx0 * p_msk : 0.f;
            float w11 = (vy1 && vx1) ? wy1 * wx1 * p_msk : 0.f;

            int yc0 = min(max(y0, 0), HH - 1), yc1 = min(max(y1, 0), HH - 1);
            int xc0 = min(max(x0, 0), WW - 1), xc1 = min(max(x1, 0), WW - 1);

            if (lane < 16) {
                sIdx[pixW] = make_int4(yc0 * WW + xc0, yc0 * WW + xc1,
                                       yc1 * WW + xc0, yc1 * WW + xc1);
                sWt[pixW]  = make_float4(w00, w01, w10, w11);
            }
        }
        __syncwarp();   // params (warp-private) visible warp-wide

        // ---- warp-cooperative sampling ----
#pragma unroll 4
        for (int pi = 0; pi < 16; pi++) {
            const int p = wrp * 16 + pi;
            int4   idx = sIdx[p];
            float4 wt  = sWt[p];

            float2 a00 = *(const float2*)(xb + (size_t)idx.x * CC + 2 * lane);
            float2 a01 = *(const float2*)(xb + (size_t)idx.y * CC + 2 * lane);
            float2 a10 = *(const float2*)(xb + (size_t)idx.z * CC + 2 * lane);
            float2 a11 = *(const float2*)(xb + (size_t)idx.w * CC + 2 * lane);

            float s0 = fmaf(wt.w, a11.x, fmaf(wt.z, a10.x, fmaf(wt.y, a01.x, wt.x * a00.x)));
            float s1 = fmaf(wt.w, a11.y, fmaf(wt.z, a10.y, fmaf(wt.y, a01.y, wt.x * a00.y)));

            uint32_t hp, lp;
            split_pack(s0, s1, hp, lp);
            uint32_t so = (uint32_t)(p * 128)
                        + (((lane_chunk ^ (uint32_t)(p & 7)) << 4) | lane_rem);
            *(uint32_t*)(smb +          so) = hp;
            *(uint32_t*)(smb + 16384 + so) = lp;
        }
        __syncwarp();   // A-tile rows (warp-private) visible warp-wide

        // prefetch next tap's params (hides under mma)
        if (k + 1 < K2) {
            p_offy = g_offset[(b * OFFC + 2 * (k + 1)    ) * HWP + pixT];
            p_offx = g_offset[(b * OFFC + 2 * (k + 1) + 1) * HWP + pixT];
            p_msk  = g_mask  [(b * MASKC + (k + 1)       ) * HWP + pixT];
        }

        // ---- mma with B-reuse: Wh -> (hi, lo), Wl -> hi ----
        uint32_t afrh[4][4], afrl[4][4];
#pragma unroll
        for (int kk = 0; kk < 4; kk++) {
            ldm_x4(afrh[kk], uAhi + lda[kk]);
            ldm_x4(afrl[kk], uAlo + lda[kk]);
        }

        const uint2* wfH = (const uint2*)(smb + wfOff) + lane;
        const uint2* wfL = wfH + 1024;
#pragma unroll
        for (int kk = 0; kk < 4; kk++) {
#pragma unroll
            for (int grp = 0; grp < 8; grp += 4) {
                uint2 bh[4];
#pragma unroll
                for (int j = 0; j < 4; j++)
                    bh[j] = wfH[(grp + j) * 128 + kk * 32];
#pragma unroll
                for (int j = 0; j < 4; j++)
                    mma16816(acc + (grp + j) * 4, afrh[kk], &bh[j].x);
#pragma unroll
                for (int j = 0; j < 4; j++)
                    mma16816(acc + (grp + j) * 4, afrl[kk], &bh[j].x);
                uint2 bl[4];
#pragma unroll
                for (int j = 0; j < 4; j++)
                    bl[j] = wfL[(grp + j) * 128 + kk * 32];
#pragma unroll
                for (int j = 0; j < 4; j++)
                    mma16816(acc + (grp + j) * 4, afrh[kk], &bl[j].x);
            }
        }
    }

    float* ob = out + (size_t)b * CC * HWP + h * WW;
    {
        const int m = wrp * 16 + (lane >> 2);
#pragma unroll
        for (int nn = 0; nn < 8; nn++) {
            int n = nn * 8 + 2 * (lane & 3);
            const float* a = acc + nn * 4;
            ob[(size_t)n * HWP + m]           = a[0];
            ob[(size_t)(n + 1) * HWP + m]     = a[1];
            ob[(size_t)n * HWP + m + 8]       = a[2];
            ob[(size_t)(n + 1) * HWP + m + 8] = a[3];
        }
    }
}

// ---------------------------------------------------------------------------
extern "C" void kernel_launch(void* const* d_in, const int* in_sizes, int n_in,
                              void* d_out, int out_size)
{
    const float* x      = (const float*)d_in[0];
    const float* w_conv = (const float*)d_in[1];
    const float* w_off  = (const float*)d_in[2];
    const float* w_msk  = (const float*)d_in[3];

    static bool attr_set = false;
    if (!attr_set) {
        cudaFuncSetAttribute(deform_kernel,
                             cudaFuncAttributeMaxDynamicSharedMemorySize,
                             SMEM_BYTES);
        cudaFuncSetAttribute(offmask_kernel,
                             cudaFuncAttributeMaxDynamicSharedMemorySize,
                             OM_SMEM);
        attr_set = true;
    }

    nhwc_kernel<<<dim3(HWP / 32, CC / 32, BB), dim3(32, 8)>>>(x);
    wfrag_kernel<<<(K2 * 2 * 8 * 4 * 32 + 255) / 256, 256>>>(w_conv);
    ofrag_kernel<<<(K2 * 2 * 4 * 4 * 32 + 255) / 256, 256>>>(w_off, w_msk);
    offmask_kernel<<<dim3(HH, BB), 128, OM_SMEM>>>();
    deform_kernel<<<dim3(HH, BB), 256, SMEM_BYTES>>>((float*)d_out);
}

// round 16
// speedup vs baseline: 1.0476x; 1.0476x over previous
#include <cuda_runtime.h>
#include <cuda_bf16.h>
#include <cstdint>

#define BB 8
#define CC 64
#define HH 128
#define WW 128
#define HWP (HH*WW)
#define K2 9
#define OFFC 18
#define MASKC 9
#define NOUT 27

// ---------------------------------------------------------------------------
// Device scratch (graph-safe)
// ---------------------------------------------------------------------------
__device__ float g_offset[BB * OFFC * HWP];
__device__ float g_mask  [BB * MASKC * HWP];
__device__ float g_xt    [(size_t)BB * HWP * CC];   // x in NHWC (33.5 MB)
// deform W fragments: [tap][hi/lo][nn(8)][kk(4)][lane(32)] x uint2
__device__ __align__(16) uint2 g_wfrag[K2 * 2 * 8 * 4 * 32];
// offset/mask W fragments (N padded 27->32): [tap][hi/lo][nn(4)][kk(4)][lane(32)]
__device__ __align__(16) uint2 g_ofrag[K2 * 2 * 4 * 4 * 32];

#define WFRAG_N (K2 * 2 * 8 * 4 * 32)   // 9216
#define OFRAG_N (K2 * 2 * 4 * 4 * 32)   // 4608

__device__ __forceinline__ uint32_t smem_u32(const void* p) {
    uint32_t a;
    asm("{ .reg .u64 t; cvta.to.shared.u64 t, %1; cvt.u32.u64 %0, t; }" : "=r"(a) : "l"(p));
    return a;
}

__device__ __forceinline__ void ldm_x4(uint32_t* r, uint32_t addr) {
    asm volatile("ldmatrix.sync.aligned.m8n8.x4.shared.b16 {%0,%1,%2,%3}, [%4];"
        : "=r"(r[0]), "=r"(r[1]), "=r"(r[2]), "=r"(r[3]) : "r"(addr));
}

__device__ __forceinline__ void mma16816(float* d, const uint32_t* a, const uint32_t* b) {
    asm volatile(
        "mma.sync.aligned.m16n8k16.row.col.f32.bf16.bf16.f32 "
        "{%0,%1,%2,%3}, {%4,%5,%6,%7}, {%8,%9}, {%0,%1,%2,%3};"
        : "+f"(d[0]), "+f"(d[1]), "+f"(d[2]), "+f"(d[3])
        : "r"(a[0]), "r"(a[1]), "r"(a[2]), "r"(a[3]), "r"(b[0]), "r"(b[1]));
}

__device__ __forceinline__ void split_pack(float s0, float s1,
                                           uint32_t& hp, uint32_t& lp) {
    __nv_bfloat16 h0 = __float2bfloat16(s0);
    __nv_bfloat16 h1 = __float2bfloat16(s1);
    __nv_bfloat16 l0 = __float2bfloat16(s0 - __bfloat162float(h0));
    __nv_bfloat16 l1 = __float2bfloat16(s1 - __bfloat162float(h1));
    hp = (uint32_t)__bfloat16_as_ushort(h0) | ((uint32_t)__bfloat16_as_ushort(h1) << 16);
    lp = (uint32_t)__bfloat16_as_ushort(l0) | ((uint32_t)__bfloat16_as_ushort(l1) << 16);
}

#define CP_ASYNC16(dst, src) \
    asm volatile("cp.async.cg.shared.global [%0], [%1], 16;" :: "r"(dst), "l"(src) : "memory")
#define CP_COMMIT() asm volatile("cp.async.commit_group;" ::: "memory")
#define CP_WAIT0()  asm volatile("cp.async.wait_group 0;" ::: "memory")

// ---------------------------------------------------------------------------
// NCHW -> NHWC transpose via smem tiles
// ---------------------------------------------------------------------------
__global__ __launch_bounds__(256) void nhwc_kernel(const float* __restrict__ x)
{
    __shared__ float tile[32][33];
    const int b  = blockIdx.z;
    const int c0 = blockIdx.y * 32;
    const int p0 = blockIdx.x * 32;
    const int tx = threadIdx.x, ty = threadIdx.y;

#pragma unroll
    for (int i = 0; i < 4; i++)
        tile[ty + 8 * i][tx] = x[((size_t)b * CC + c0 + ty + 8 * i) * HWP + p0 + tx];
    __syncthreads();
#pragma unroll
    for (int i = 0; i < 4; i++)
        g_xt[((size_t)b * HWP + p0 + ty + 8 * i) * CC + c0 + tx] = tile[tx][ty + 8 * i];
}

// ---------------------------------------------------------------------------
// Merged setup: deform W fragments + offset/mask W fragments in one launch
// ---------------------------------------------------------------------------
__global__ void frag_kernel(const float* __restrict__ w_conv,
                            const float* __restrict__ w_off,
                            const float* __restrict__ w_msk)
{
    int i = blockIdx.x * 256 + threadIdx.x;
    if (i < WFRAG_N) {
        int lane = i & 31;
        int kk   = (i >> 5) & 3;
        int nn   = (i >> 7) & 7;
        int hl   = (i >> 10) & 1;
        int k    = i >> 11;

        int co    = nn * 8 + (lane >> 2);
        int cbase = kk * 16 + 2 * (lane & 3);

        uint32_t regs[2];
#pragma unroll
        for (int r = 0; r < 2; r++) {
            uint32_t pk = 0;
#pragma unroll
            for (int j = 0; j < 2; j++) {
                int c = cbase + r * 8 + j;
                float wv = w_conv[(co * CC + c) * K2 + k];
                __nv_bfloat16 hi = __float2bfloat16(wv);
                float lov = wv - __bfloat162float(hi);
                __nv_bfloat16 v = hl ? __float2bfloat16(lov) : hi;
                pk |= ((uint32_t)__bfloat16_as_ushort(v)) << (16 * j);
            }
            regs[r] = pk;
        }
        g_wfrag[i] = make_uint2(regs[0], regs[1]);
    } else if (i < WFRAG_N + OFRAG_N) {
        int q = i - WFRAG_N;
        int lane = q & 31;
        int kk   = (q >> 5) & 3;
        int nn   = (q >> 7) & 3;
        int hl   = (q >> 9) & 1;
        int k    = q >> 10;

        int co    = nn * 8 + (lane >> 2);
        int cbase = kk * 16 + 2 * (lane & 3);

        uint32_t regs[2];
#pragma unroll
        for (int r = 0; r < 2; r++) {
            uint32_t pk = 0;
#pragma unroll
            for (int j = 0; j < 2; j++) {
                int c = cbase + r * 8 + j;
                float wv = 0.f;
                if (co < OFFC)      wv = w_off[(co * CC + c) * K2 + k];
                else if (co < NOUT) wv = w_msk[((co - OFFC) * CC + c) * K2 + k];
                __nv_bfloat16 hi = __float2bfloat16(wv);
                float lov = wv - __bfloat162float(hi);
                __nv_bfloat16 v = hl ? __float2bfloat16(lov) : hi;
                pk |= ((uint32_t)__bfloat16_as_ushort(v)) << (16 * j);
            }
            regs[r] = pk;
        }
        g_ofrag[q] = make_uint2(regs[0], regs[1]);
    }
}

// ---------------------------------------------------------------------------
// Kernel 1: offset/mask conv via mma.sync (round-14 version, proven 77.2 us)
// ---------------------------------------------------------------------------
#define OM_WBYTES (2 * 34 * 128)             // hi+lo window per warp (8704 B)
#define OM_SMEM   (4 * OM_WBYTES + 1024)

__global__ __launch_bounds__(128) void offmask_kernel()
{
    extern __shared__ char smraw[];
    const uint32_t raw_u  = smem_u32(smraw);
    const uint32_t base_u = (raw_u + 1023) & ~1023u;
    char* const smb = smraw + (base_u - raw_u);

    const int t    = threadIdx.x;
    const int lane = t & 31;
    const int wrp  = t >> 5;
    const int h    = blockIdx.x;
    const int b    = blockIdx.y;

    char* const wt_hi = smb + wrp * OM_WBYTES;
    char* const wt_lo = wt_hi + 34 * 128;
    const uint32_t uHi = base_u + wrp * OM_WBYTES;
    const uint32_t uLo = uHi + 34 * 128;

    float acc[32];
#pragma unroll
    for (int i = 0; i < 32; i++) acc[i] = 0.f;

    const float* xb = g_xt + (size_t)b * HWP * CC;
    const uint32_t lane_chunk = lane >> 2;
    const uint32_t lane_rem   = (lane & 3) << 2;
    const int p0 = wrp * 32 - 1;

#pragma unroll 1
    for (int ki = 0; ki < 3; ki++) {
        const int yy = h + ki - 1;
        const bool yok = (yy >= 0) && (yy < HH);

        __syncwarp();
#pragma unroll 2
        for (int pi = 0; pi < 34; pi++) {
            const int q = p0 + pi;
            float2 a = make_float2(0.f, 0.f);
            if (yok && q >= 0 && q < WW)
                a = *(const float2*)(xb + (size_t)(yy * WW + q) * CC + 2 * lane);
            uint32_t hp, lp;
            split_pack(a.x, a.y, hp, lp);
            uint32_t so = (uint32_t)(pi * 128)
                        + (((lane_chunk ^ (uint32_t)(pi & 7)) << 4) | lane_rem);
            *(uint32_t*)(wt_hi + so) = hp;
            *(uint32_t*)(wt_lo + so) = lp;
        }
        __syncwarp();

#pragma unroll 1
        for (int kj = 0; kj < 3; kj++) {
            const int k = ki * 3 + kj;
            const uint2* wfb = g_ofrag + (size_t)k * 1024 + lane;

            uint32_t afrh[2][4][4], afrl[2][4][4];
#pragma unroll
            for (int mt = 0; mt < 2; mt++) {
                const int rs = mt * 16 + (lane & 15) + kj;
                const uint32_t rb = (uint32_t)(rs * 128);
                const uint32_t r7 = (uint32_t)(rs & 7);
#pragma unroll
                for (int kk = 0; kk < 4; kk++) {
                    uint32_t chunk = (uint32_t)(kk * 2) + (uint32_t)(lane >> 4);
                    ldm_x4(afrh[mt][kk], uHi + rb + ((chunk ^ r7) << 4));
                    ldm_x4(afrl[mt][kk], uLo + rb + ((chunk ^ r7) << 4));
                }
            }

#pragma unroll
            for (int kk = 0; kk < 4; kk++) {
                uint2 bh[4];
#pragma unroll
                for (int j = 0; j < 4; j++)
                    bh[j] = __ldg(wfb + j * 128 + kk * 32);
#pragma unroll
                for (int j = 0; j < 4; j++) {
                    mma16816(acc + (0 * 4 + j) * 4, afrh[0][kk], &bh[j].x);
                    mma16816(acc + (1 * 4 + j) * 4, afrh[1][kk], &bh[j].x);
                }
#pragma unroll
                for (int j = 0; j < 4; j++) {
                    mma16816(acc + (0 * 4 + j) * 4, afrl[0][kk], &bh[j].x);
                    mma16816(acc + (1 * 4 + j) * 4, afrl[1][kk], &bh[j].x);
                }
                uint2 bl[4];
#pragma unroll
                for (int j = 0; j < 4; j++)
                    bl[j] = __ldg(wfb + 512 + j * 128 + kk * 32);
#pragma unroll
                for (int j = 0; j < 4; j++) {
                    mma16816(acc + (0 * 4 + j) * 4, afrh[0][kk], &bl[j].x);
                    mma16816(acc + (1 * 4 + j) * 4, afrh[1][kk], &bl[j].x);
                }
            }
        }
    }

#pragma unroll
    for (int mt = 0; mt < 2; mt++) {
        int m = wrp * 32 + mt * 16 + (lane >> 2);
#pragma unroll
        for (int nn = 0; nn < 4; nn++) {
            int n = nn * 8 + 2 * (lane & 3);
            const float* a = acc + (mt * 4 + nn) * 4;
#pragma unroll
            for (int q = 0; q < 4; q++) {
                int ch = n + (q & 1);
                int mm = m + (q >> 1) * 8;
                float v = a[q];
                int pix = h * WW + mm;
                if (ch < OFFC)
                    g_offset[(b * OFFC + ch) * HWP + pix] = v;
                else if (ch < NOUT)
                    g_mask[(b * MASKC + ch - OFFC) * HWP + pix] =
                        1.f / (1.f + __expf(-v));
            }
        }
    }
}

// ---------------------------------------------------------------------------
// Kernel 2: deform — round-14 version (proven): 256 threads / 8 warps,
// cp.async double-buffered W, B-reuse mma, t<128 param phase.
// ---------------------------------------------------------------------------
#define SM_WF0     32768
#define SM_WF1     49152
#define SM_IDX_OFF 65536
#define SM_WT_OFF  (65536 + 2048)
#define SMEM_BYTES (65536 + 4096 + 1024)

__global__ __launch_bounds__(256, 3) void deform_kernel(float* __restrict__ out)
{
    extern __shared__ char smraw[];
    const uint32_t raw_u  = smem_u32(smraw);
    const uint32_t base_u = (raw_u + 1023) & ~1023u;
    char* const smb = smraw + (base_u - raw_u);

    const uint32_t uAhi = base_u;            // 16 KB hi A-tile [128px][64c]
    const uint32_t uAlo = base_u + 16384;    // 16 KB lo A-tile
    int4*   const sIdx = (int4*)(smb + SM_IDX_OFF);
    float4* const sWt  = (float4*)(smb + SM_WT_OFF);

    const int t    = threadIdx.x;
    const int lane = t & 31;
    const int wrp  = t >> 5;
    const int h    = blockIdx.x;
    const int b    = blockIdx.y;

    float acc[32];
#pragma unroll
    for (int i = 0; i < 32; i++) acc[i] = 0.f;

    const float* xb = g_xt + (size_t)b * HWP * CC;

    uint32_t lda[4];
    {
        const int r = wrp * 16 + (lane & 15);
#pragma unroll
        for (int kk = 0; kk < 4; kk++) {
            int chunk = kk * 2 + (lane >> 4);
            lda[kk] = (uint32_t)(r * 128 + ((chunk ^ (r & 7)) * 16));
        }
    }
    const uint32_t lane_chunk = lane >> 2;
    const uint32_t lane_rem   = (lane & 3) << 2;

    const int pixT = h * WW + (t & 127);
    float p_offy = g_offset[(b * OFFC + 0) * HWP + pixT];
    float p_offx = g_offset[(b * OFFC + 1) * HWP + pixT];
    float p_msk  = g_mask  [(b * MASKC + 0) * HWP + pixT];

    // pre-loop: async-stage W(0) into buffer 0
    {
        const char* src = (const char*)(g_wfrag) + 0;
#pragma unroll
        for (int i = 0; i < 4; i++)
            CP_ASYNC16(base_u + SM_WF0 + (t + 256 * i) * 16,
                       src + (t + 256 * i) * 16);
        CP_COMMIT();
    }

#pragma unroll 1
    for (int k = 0; k < K2; k++) {
        CP_WAIT0();
        __syncthreads();   // W(k) landed + prior buffer readers done

        const uint32_t wfOff = (k & 1) ? SM_WF1 : SM_WF0;

        // ---- bilinear params for pixel t&127 ----
        {
            const int w = t & 127;
            const int ki = k / 3, kj = k % 3;
            float py = (float)(h + ki - 1) + p_offy;
            float px = (float)(w + kj - 1) + p_offx;
            float y0f = floorf(py), x0f = floorf(px);
            int   y0 = (int)y0f,    x0 = (int)x0f;
            int   y1 = y0 + 1,      x1 = x0 + 1;
            float wy1 = py - y0f,   wx1 = px - x0f;
            float wy0 = 1.f - wy1,  wx0 = 1.f - wx1;

            bool vy0 = (y0 >= 0) && (y0 < HH), vy1 = (y1 >= 0) && (y1 < HH);
            bool vx0 = (x0 >= 0) && (x0 < WW), vx1 = (x1 >= 0) && (x1 < WW);

            float w00 = (vy0 && vx0) ? wy0 * wx0 * p_msk : 0.f;
            float w01 = (vy0 && vx1) ? wy0 * wx1 * p_msk : 0.f;
            float w10 = (vy1 && vx0) ? wy1 * wx0 * p_msk : 0.f;
            float w11 = (vy1 && vx1) ? wy1 * wx1 * p_msk : 0.f;

            int yc0 = min(max(y0, 0), HH - 1), yc1 = min(max(y1, 0), HH - 1);
            int xc0 = min(max(x0, 0), WW - 1), xc1 = min(max(x1, 0), WW - 1);

            if (t < 128) {
                sIdx[t] = make_int4(yc0 * WW + xc0, yc0 * WW + xc1,
                                    yc1 * WW + xc0, yc1 * WW + xc1);
                sWt[t]  = make_float4(w00, w01, w10, w11);
            }
        }

        // ---- async-stage W(k+1) into the other buffer ----
        if (k + 1 < K2) {
            const char* src = (const char*)(g_wfrag + (size_t)(k + 1) * 2048);
            const uint32_t dst = base_u + (((k + 1) & 1) ? SM_WF1 : SM_WF0);
#pragma unroll
            for (int i = 0; i < 4; i++)
                CP_ASYNC16(dst + (t + 256 * i) * 16, src + (t + 256 * i) * 16);
            CP_COMMIT();
        }
        __syncthreads();   // params ready

        // ---- warp-cooperative sampling ----
#pragma unroll 4
        for (int pi = 0; pi < 16; pi++) {
            const int p = wrp * 16 + pi;
            int4   idx = sIdx[p];
            float4 wt  = sWt[p];

            float2 a00 = *(const float2*)(xb + (size_t)idx.x * CC + 2 * lane);
            float2 a01 = *(const float2*)(xb + (size_t)idx.y * CC + 2 * lane);
            float2 a10 = *(const float2*)(xb + (size_t)idx.z * CC + 2 * lane);
            float2 a11 = *(const float2*)(xb + (size_t)idx.w * CC + 2 * lane);

            float s0 = fmaf(wt.w, a11.x, fmaf(wt.z, a10.x, fmaf(wt.y, a01.x, wt.x * a00.x)));
            float s1 = fmaf(wt.w, a11.y, fmaf(wt.z, a10.y, fmaf(wt.y, a01.y, wt.x * a00.y)));

            uint32_t hp, lp;
            split_pack(s0, s1, hp, lp);
            uint32_t so = (uint32_t)(p * 128)
                        + (((lane_chunk ^ (uint32_t)(p & 7)) << 4) | lane_rem);
            *(uint32_t*)(smb +          so) = hp;
            *(uint32_t*)(smb + 16384 + so) = lp;
        }
        __syncwarp();

        // prefetch next tap's params
        if (k + 1 < K2) {
            p_offy = g_offset[(b * OFFC + 2 * (k + 1)    ) * HWP + pixT];
            p_offx = g_offset[(b * OFFC + 2 * (k + 1) + 1) * HWP + pixT];
            p_msk  = g_mask  [(b * MASKC + (k + 1)       ) * HWP + pixT];
        }

        // ---- mma with B-reuse: Wh -> (hi, lo), Wl -> hi ----
        uint32_t afrh[4][4], afrl[4][4];
#pragma unroll
        for (int kk = 0; kk < 4; kk++) {
            ldm_x4(afrh[kk], uAhi + lda[kk]);
            ldm_x4(afrl[kk], uAlo + lda[kk]);
        }

        const uint2* wfH = (const uint2*)(smb + wfOff) + lane;
        const uint2* wfL = wfH + 1024;
#pragma unroll
        for (int kk = 0; kk < 4; kk++) {
#pragma unroll
            for (int grp = 0; grp < 8; grp += 4) {
                uint2 bh[4];
#pragma unroll
                for (int j = 0; j < 4; j++)
                    bh[j] = wfH[(grp + j) * 128 + kk * 32];
#pragma unroll
                for (int j = 0; j < 4; j++)
                    mma16816(acc + (grp + j) * 4, afrh[kk], &bh[j].x);
#pragma unroll
                for (int j = 0; j < 4; j++)
                    mma16816(acc + (grp + j) * 4, afrl[kk], &bh[j].x);
                uint2 bl[4];
#pragma unroll
                for (int j = 0; j < 4; j++)
                    bl[j] = wfL[(grp + j) * 128 + kk * 32];
#pragma unroll
                for (int j = 0; j < 4; j++)
                    mma16816(acc + (grp + j) * 4, afrh[kk], &bl[j].x);
            }
        }
    }

    float* ob = out + (size_t)b * CC * HWP + h * WW;
    {
        const int m = wrp * 16 + (lane >> 2);
#pragma unroll
        for (int nn = 0; nn < 8; nn++) {
            int n = nn * 8 + 2 * (lane & 3);
            const float* a = acc + nn * 4;
            ob[(size_t)n * HWP + m]           = a[0];
            ob[(size_t)(n + 1) * HWP + m]     = a[1];
            ob[(size_t)n * HWP + m + 8]       = a[2];
            ob[(size_t)(n + 1) * HWP + m + 8] = a[3];
        }
    }
}

// ---------------------------------------------------------------------------
extern "C" void kernel_launch(void* const* d_in, const int* in_sizes, int n_in,
                              void* d_out, int out_size)
{
    const float* x      = (const float*)d_in[0];
    const float* w_conv = (const float*)d_in[1];
    const float* w_off  = (const float*)d_in[2];
    const float* w_msk  = (const float*)d_in[3];

    static bool attr_set = false;
    if (!attr_set) {
        cudaFuncSetAttribute(deform_kernel,
                             cudaFuncAttributeMaxDynamicSharedMemorySize,
                             SMEM_BYTES);
        cudaFuncSetAttribute(offmask_kernel,
                             cudaFuncAttributeMaxDynamicSharedMemorySize,
                             OM_SMEM);
        attr_set = true;
    }

    nhwc_kernel<<<dim3(HWP / 32, CC / 32, BB), dim3(32, 8)>>>(x);
    frag_kernel<<<(WFRAG_N + OFRAG_N + 255) / 256, 256>>>(w_conv, w_off, w_msk);
    offmask_kernel<<<dim3(HH, BB), 128, OM_SMEM>>>();
    deform_kernel<<<dim3(HH, BB), 256, SMEM_BYTES>>>((float*)d_out);
}

// round 17
// speedup vs baseline: 1.2398x; 1.1835x over previous
#include <cuda_runtime.h>
#include <cuda_bf16.h>
#include <cuda_fp16.h>
#include <cstdint>

#define BB 8
#define CC 64
#define HH 128
#define WW 128
#define HWP (HH*WW)
#define K2 9
#define OFFC 18
#define MASKC 9
#define NOUT 27

// ---------------------------------------------------------------------------
// Device scratch (graph-safe)
// ---------------------------------------------------------------------------
__device__ float g_offset[BB * OFFC * HWP];
__device__ float g_mask  [BB * MASKC * HWP];
__device__ float g_xt    [(size_t)BB * HWP * CC];   // x in NHWC (33.5 MB)
// deform W fragments (fp16, single): [tap][nn(8)][kk(4)][lane(32)] x uint2
__device__ __align__(16) uint2 g_wfrag[K2 * 8 * 4 * 32];
// offset/mask W fragments (bf16 hi/lo, N padded 27->32): [tap][hi/lo][nn(4)][kk(4)][lane(32)]
__device__ __align__(16) uint2 g_ofrag[K2 * 2 * 4 * 4 * 32];

#define WFRAG_N (K2 * 8 * 4 * 32)       // 9216 -> now 4608
#define OFRAG_N (K2 * 2 * 4 * 4 * 32)   // 4608

__device__ __forceinline__ uint32_t smem_u32(const void* p) {
    uint32_t a;
    asm("{ .reg .u64 t; cvta.to.shared.u64 t, %1; cvt.u32.u64 %0, t; }" : "=r"(a) : "l"(p));
    return a;
}

__device__ __forceinline__ void ldm_x4(uint32_t* r, uint32_t addr) {
    asm volatile("ldmatrix.sync.aligned.m8n8.x4.shared.b16 {%0,%1,%2,%3}, [%4];"
        : "=r"(r[0]), "=r"(r[1]), "=r"(r[2]), "=r"(r[3]) : "r"(addr));
}

// bf16 mma (offmask)
__device__ __forceinline__ void mma16816(float* d, const uint32_t* a, const uint32_t* b) {
    asm volatile(
        "mma.sync.aligned.m16n8k16.row.col.f32.bf16.bf16.f32 "
        "{%0,%1,%2,%3}, {%4,%5,%6,%7}, {%8,%9}, {%0,%1,%2,%3};"
        : "+f"(d[0]), "+f"(d[1]), "+f"(d[2]), "+f"(d[3])
        : "r"(a[0]), "r"(a[1]), "r"(a[2]), "r"(a[3]), "r"(b[0]), "r"(b[1]));
}

// fp16 mma (deform single-pass)
__device__ __forceinline__ void mma16816h(float* d, const uint32_t* a, const uint32_t* b) {
    asm volatile(
        "mma.sync.aligned.m16n8k16.row.col.f32.f16.f16.f32 "
        "{%0,%1,%2,%3}, {%4,%5,%6,%7}, {%8,%9}, {%0,%1,%2,%3};"
        : "+f"(d[0]), "+f"(d[1]), "+f"(d[2]), "+f"(d[3])
        : "r"(a[0]), "r"(a[1]), "r"(a[2]), "r"(a[3]), "r"(b[0]), "r"(b[1]));
}

__device__ __forceinline__ void split_pack(float s0, float s1,
                                           uint32_t& hp, uint32_t& lp) {
    __nv_bfloat16 h0 = __float2bfloat16(s0);
    __nv_bfloat16 h1 = __float2bfloat16(s1);
    __nv_bfloat16 l0 = __float2bfloat16(s0 - __bfloat162float(h0));
    __nv_bfloat16 l1 = __float2bfloat16(s1 - __bfloat162float(h1));
    hp = (uint32_t)__bfloat16_as_ushort(h0) | ((uint32_t)__bfloat16_as_ushort(h1) << 16);
    lp = (uint32_t)__bfloat16_as_ushort(l0) | ((uint32_t)__bfloat16_as_ushort(l1) << 16);
}

__device__ __forceinline__ uint32_t pack_half2(float s0, float s1) {
    __half h0 = __float2half(s0), h1 = __float2half(s1);
    return (uint32_t)__half_as_ushort(h0) | ((uint32_t)__half_as_ushort(h1) << 16);
}

#define CP_ASYNC16(dst, src) \
    asm volatile("cp.async.cg.shared.global [%0], [%1], 16;" :: "r"(dst), "l"(src) : "memory")
#define CP_COMMIT() asm volatile("cp.async.commit_group;" ::: "memory")
#define CP_WAIT0()  asm volatile("cp.async.wait_group 0;" ::: "memory")

// ---------------------------------------------------------------------------
// NCHW -> NHWC transpose via smem tiles
// ---------------------------------------------------------------------------
__global__ __launch_bounds__(256) void nhwc_kernel(const float* __restrict__ x)
{
    __shared__ float tile[32][33];
    const int b  = blockIdx.z;
    const int c0 = blockIdx.y * 32;
    const int p0 = blockIdx.x * 32;
    const int tx = threadIdx.x, ty = threadIdx.y;

#pragma unroll
    for (int i = 0; i < 4; i++)
        tile[ty + 8 * i][tx] = x[((size_t)b * CC + c0 + ty + 8 * i) * HWP + p0 + tx];
    __syncthreads();
#pragma unroll
    for (int i = 0; i < 4; i++)
        g_xt[((size_t)b * HWP + p0 + ty + 8 * i) * CC + c0 + tx] = tile[tx][ty + 8 * i];
}

// ---------------------------------------------------------------------------
// Merged setup: deform fp16 W fragments + offset/mask bf16 hi/lo fragments
// ---------------------------------------------------------------------------
__global__ void frag_kernel(const float* __restrict__ w_conv,
                            const float* __restrict__ w_off,
                            const float* __restrict__ w_msk)
{
    int i = blockIdx.x * 256 + threadIdx.x;
    if (i < WFRAG_N) {
        int lane = i & 31;
        int kk   = (i >> 5) & 3;
        int nn   = (i >> 7) & 7;
        int k    = i >> 10;

        int co    = nn * 8 + (lane >> 2);
        int cbase = kk * 16 + 2 * (lane & 3);

        uint32_t regs[2];
#pragma unroll
        for (int r = 0; r < 2; r++) {
            uint32_t pk = 0;
#pragma unroll
            for (int j = 0; j < 2; j++) {
                int c = cbase + r * 8 + j;
                float wv = w_conv[(co * CC + c) * K2 + k];
                __half v = __float2half(wv);
                pk |= ((uint32_t)__half_as_ushort(v)) << (16 * j);
            }
            regs[r] = pk;
        }
        g_wfrag[i] = make_uint2(regs[0], regs[1]);
    } else if (i < WFRAG_N + OFRAG_N) {
        int q = i - WFRAG_N;
        int lane = q & 31;
        int kk   = (q >> 5) & 3;
        int nn   = (q >> 7) & 3;
        int hl   = (q >> 9) & 1;
        int k    = q >> 10;

        int co    = nn * 8 + (lane >> 2);
        int cbase = kk * 16 + 2 * (lane & 3);

        uint32_t regs[2];
#pragma unroll
        for (int r = 0; r < 2; r++) {
            uint32_t pk = 0;
#pragma unroll
            for (int j = 0; j < 2; j++) {
                int c = cbase + r * 8 + j;
                float wv = 0.f;
                if (co < OFFC)      wv = w_off[(co * CC + c) * K2 + k];
                else if (co < NOUT) wv = w_msk[((co - OFFC) * CC + c) * K2 + k];
                __nv_bfloat16 hi = __float2bfloat16(wv);
                float lov = wv - __bfloat162float(hi);
                __nv_bfloat16 v = hl ? __float2bfloat16(lov) : hi;
                pk |= ((uint32_t)__bfloat16_as_ushort(v)) << (16 * j);
            }
            regs[r] = pk;
        }
        g_ofrag[q] = make_uint2(regs[0], regs[1]);
    }
}

// ---------------------------------------------------------------------------
// Kernel 1: offset/mask conv via mma.sync (round-14 version, proven 77.2 us)
// ---------------------------------------------------------------------------
#define OM_WBYTES (2 * 34 * 128)
#define OM_SMEM   (4 * OM_WBYTES + 1024)

__global__ __launch_bounds__(128) void offmask_kernel()
{
    extern __shared__ char smraw[];
    const uint32_t raw_u  = smem_u32(smraw);
    const uint32_t base_u = (raw_u + 1023) & ~1023u;
    char* const smb = smraw + (base_u - raw_u);

    const int t    = threadIdx.x;
    const int lane = t & 31;
    const int wrp  = t >> 5;
    const int h    = blockIdx.x;
    const int b    = blockIdx.y;

    char* const wt_hi = smb + wrp * OM_WBYTES;
    char* const wt_lo = wt_hi + 34 * 128;
    const uint32_t uHi = base_u + wrp * OM_WBYTES;
    const uint32_t uLo = uHi + 34 * 128;

    float acc[32];
#pragma unroll
    for (int i = 0; i < 32; i++) acc[i] = 0.f;

    const float* xb = g_xt + (size_t)b * HWP * CC;
    const uint32_t lane_chunk = lane >> 2;
    const uint32_t lane_rem   = (lane & 3) << 2;
    const int p0 = wrp * 32 - 1;

#pragma unroll 1
    for (int ki = 0; ki < 3; ki++) {
        const int yy = h + ki - 1;
        const bool yok = (yy >= 0) && (yy < HH);

        __syncwarp();
#pragma unroll 2
        for (int pi = 0; pi < 34; pi++) {
            const int q = p0 + pi;
            float2 a = make_float2(0.f, 0.f);
            if (yok && q >= 0 && q < WW)
                a = *(const float2*)(xb + (size_t)(yy * WW + q) * CC + 2 * lane);
            uint32_t hp, lp;
            split_pack(a.x, a.y, hp, lp);
            uint32_t so = (uint32_t)(pi * 128)
                        + (((lane_chunk ^ (uint32_t)(pi & 7)) << 4) | lane_rem);
            *(uint32_t*)(wt_hi + so) = hp;
            *(uint32_t*)(wt_lo + so) = lp;
        }
        __syncwarp();

#pragma unroll 1
        for (int kj = 0; kj < 3; kj++) {
            const int k = ki * 3 + kj;
            const uint2* wfb = g_ofrag + (size_t)k * 1024 + lane;

            uint32_t afrh[2][4][4], afrl[2][4][4];
#pragma unroll
            for (int mt = 0; mt < 2; mt++) {
                const int rs = mt * 16 + (lane & 15) + kj;
                const uint32_t rb = (uint32_t)(rs * 128);
                const uint32_t r7 = (uint32_t)(rs & 7);
#pragma unroll
                for (int kk = 0; kk < 4; kk++) {
                    uint32_t chunk = (uint32_t)(kk * 2) + (uint32_t)(lane >> 4);
                    ldm_x4(afrh[mt][kk], uHi + rb + ((chunk ^ r7) << 4));
                    ldm_x4(afrl[mt][kk], uLo + rb + ((chunk ^ r7) << 4));
                }
            }

#pragma unroll
            for (int kk = 0; kk < 4; kk++) {
                uint2 bh[4];
#pragma unroll
                for (int j = 0; j < 4; j++)
                    bh[j] = __ldg(wfb + j * 128 + kk * 32);
#pragma unroll
                for (int j = 0; j < 4; j++) {
                    mma16816(acc + (0 * 4 + j) * 4, afrh[0][kk], &bh[j].x);
                    mma16816(acc + (1 * 4 + j) * 4, afrh[1][kk], &bh[j].x);
                }
#pragma unroll
                for (int j = 0; j < 4; j++) {
                    mma16816(acc + (0 * 4 + j) * 4, afrl[0][kk], &bh[j].x);
                    mma16816(acc + (1 * 4 + j) * 4, afrl[1][kk], &bh[j].x);
                }
                uint2 bl[4];
#pragma unroll
                for (int j = 0; j < 4; j++)
                    bl[j] = __ldg(wfb + 512 + j * 128 + kk * 32);
#pragma unroll
                for (int j = 0; j < 4; j++) {
                    mma16816(acc + (0 * 4 + j) * 4, afrh[0][kk], &bl[j].x);
                    mma16816(acc + (1 * 4 + j) * 4, afrh[1][kk], &bl[j].x);
                }
            }
        }
    }

#pragma unroll
    for (int mt = 0; mt < 2; mt++) {
        int m = wrp * 32 + mt * 16 + (lane >> 2);
#pragma unroll
        for (int nn = 0; nn < 4; nn++) {
            int n = nn * 8 + 2 * (lane & 3);
            const float* a = acc + (mt * 4 + nn) * 4;
#pragma unroll
            for (int q = 0; q < 4; q++) {
                int ch = n + (q & 1);
                int mm = m + (q >> 1) * 8;
                float v = a[q];
                int pix = h * WW + mm;
                if (ch < OFFC)
                    g_offset[(b * OFFC + ch) * HWP + pix] = v;
                else if (ch < NOUT)
                    g_mask[(b * MASKC + ch - OFFC) * HWP + pix] =
                        1.f / (1.f + __expf(-v));
            }
        }
    }
}

// ---------------------------------------------------------------------------
// Kernel 2: deform — SINGLE-PASS FP16 mma. 256 threads / 8 warps, cp.async
// double-buffered W (8 KB/tap). A-tile 16 KB. One pass: S*W.
// ---------------------------------------------------------------------------
#define SM_WF0     16384
#define SM_WF1     (16384 + 8192)
#define SM_IDX_OFF 32768
#define SM_WT_OFF  (32768 + 2048)
#define SMEM_BYTES (32768 + 4096 + 1024)

__global__ __launch_bounds__(256, 3) void deform_kernel(float* __restrict__ out)
{
    extern __shared__ char smraw[];
    const uint32_t raw_u  = smem_u32(smraw);
    const uint32_t base_u = (raw_u + 1023) & ~1023u;
    char* const smb = smraw + (base_u - raw_u);

    const uint32_t uA = base_u;              // 16 KB fp16 A-tile [128px][64c]
    int4*   const sIdx = (int4*)(smb + SM_IDX_OFF);
    float4* const sWt  = (float4*)(smb + SM_WT_OFF);

    const int t    = threadIdx.x;
    const int lane = t & 31;
    const int wrp  = t >> 5;
    const int h    = blockIdx.x;
    const int b    = blockIdx.y;

    float acc[32];
#pragma unroll
    for (int i = 0; i < 32; i++) acc[i] = 0.f;

    const float* xb = g_xt + (size_t)b * HWP * CC;

    uint32_t lda[4];
    {
        const int r = wrp * 16 + (lane & 15);
#pragma unroll
        for (int kk = 0; kk < 4; kk++) {
            int chunk = kk * 2 + (lane >> 4);
            lda[kk] = (uint32_t)(r * 128 + ((chunk ^ (r & 7)) * 16));
        }
    }
    const uint32_t lane_chunk = lane >> 2;
    const uint32_t lane_rem   = (lane & 3) << 2;

    const int pixT = h * WW + (t & 127);
    float p_offy = g_offset[(b * OFFC + 0) * HWP + pixT];
    float p_offx = g_offset[(b * OFFC + 1) * HWP + pixT];
    float p_msk  = g_mask  [(b * MASKC + 0) * HWP + pixT];

    // pre-loop: async-stage W(0) into buffer 0 (8 KB)
    {
        const char* src = (const char*)(g_wfrag) + 0;
#pragma unroll
        for (int i = 0; i < 2; i++)
            CP_ASYNC16(base_u + SM_WF0 + (t + 256 * i) * 16,
                       src + (t + 256 * i) * 16);
        CP_COMMIT();
    }

#pragma unroll 1
    for (int k = 0; k < K2; k++) {
        CP_WAIT0();
        __syncthreads();   // W(k) landed + prior buffer readers done

        const uint32_t wfOff = (k & 1) ? SM_WF1 : SM_WF0;

        // ---- bilinear params for pixel t&127 ----
        {
            const int w = t & 127;
            const int ki = k / 3, kj = k % 3;
            float py = (float)(h + ki - 1) + p_offy;
            float px = (float)(w + kj - 1) + p_offx;
            float y0f = floorf(py), x0f = floorf(px);
            int   y0 = (int)y0f,    x0 = (int)x0f;
            int   y1 = y0 + 1,      x1 = x0 + 1;
            float wy1 = py - y0f,   wx1 = px - x0f;
            float wy0 = 1.f - wy1,  wx0 = 1.f - wx1;

            bool vy0 = (y0 >= 0) && (y0 < HH), vy1 = (y1 >= 0) && (y1 < HH);
            bool vx0 = (x0 >= 0) && (x0 < WW), vx1 = (x1 >= 0) && (x1 < WW);

            float w00 = (vy0 && vx0) ? wy0 * wx0 * p_msk : 0.f;
            float w01 = (vy0 && vx1) ? wy0 * wx1 * p_msk : 0.f;
            float w10 = (vy1 && vx0) ? wy1 * wx0 * p_msk : 0.f;
            float w11 = (vy1 && vx1) ? wy1 * wx1 * p_msk : 0.f;

            int yc0 = min(max(y0, 0), HH - 1), yc1 = min(max(y1, 0), HH - 1);
            int xc0 = min(max(x0, 0), WW - 1), xc1 = min(max(x1, 0), WW - 1);

            if (t < 128) {
                sIdx[t] = make_int4(yc0 * WW + xc0, yc0 * WW + xc1,
                                    yc1 * WW + xc0, yc1 * WW + xc1);
                sWt[t]  = make_float4(w00, w01, w10, w11);
            }
        }

        // ---- async-stage W(k+1) into the other buffer ----
        if (k + 1 < K2) {
            const char* src = (const char*)(g_wfrag + (size_t)(k + 1) * 1024);
            const uint32_t dst = base_u + (((k + 1) & 1) ? SM_WF1 : SM_WF0);
#pragma unroll
            for (int i = 0; i < 2; i++)
                CP_ASYNC16(dst + (t + 256 * i) * 16, src + (t + 256 * i) * 16);
            CP_COMMIT();
        }
        __syncthreads();   // params ready

        // ---- warp-cooperative sampling (fp16 pack, single tile) ----
#pragma unroll 4
        for (int pi = 0; pi < 16; pi++) {
            const int p = wrp * 16 + pi;
            int4   idx = sIdx[p];
            float4 wt  = sWt[p];

            float2 a00 = *(const float2*)(xb + (size_t)idx.x * CC + 2 * lane);
            float2 a01 = *(const float2*)(xb + (size_t)idx.y * CC + 2 * lane);
            float2 a10 = *(const float2*)(xb + (size_t)idx.z * CC + 2 * lane);
            float2 a11 = *(const float2*)(xb + (size_t)idx.w * CC + 2 * lane);

            float s0 = fmaf(wt.w, a11.x, fmaf(wt.z, a10.x, fmaf(wt.y, a01.x, wt.x * a00.x)));
            float s1 = fmaf(wt.w, a11.y, fmaf(wt.z, a10.y, fmaf(wt.y, a01.y, wt.x * a00.y)));

            uint32_t so = (uint32_t)(p * 128)
                        + (((lane_chunk ^ (uint32_t)(p & 7)) << 4) | lane_rem);
            *(uint32_t*)(smb + so) = pack_half2(s0, s1);
        }
        __syncwarp();   // A-tile rows (warp-private) visible warp-wide

        // prefetch next tap's params
        if (k + 1 < K2) {
            p_offy = g_offset[(b * OFFC + 2 * (k + 1)    ) * HWP + pixT];
            p_offx = g_offset[(b * OFFC + 2 * (k + 1) + 1) * HWP + pixT];
            p_msk  = g_mask  [(b * MASKC + (k + 1)       ) * HWP + pixT];
        }

        // ---- single fp16 mma pass ----
        uint32_t afr[4][4];
#pragma unroll
        for (int kk = 0; kk < 4; kk++)
            ldm_x4(afr[kk], uA + lda[kk]);

        const uint2* wf = (const uint2*)(smb + wfOff) + lane;
#pragma unroll
        for (int kk = 0; kk < 4; kk++) {
#pragma unroll
            for (int grp = 0; grp < 8; grp += 4) {
                uint2 bb[4];
#pragma unroll
                for (int j = 0; j < 4; j++)
                    bb[j] = wf[(grp + j) * 128 + kk * 32];
#pragma unroll
                for (int j = 0; j < 4; j++)
                    mma16816h(acc + (grp + j) * 4, afr[kk], &bb[j].x);
            }
        }
    }

    float* ob = out + (size_t)b * CC * HWP + h * WW;
    {
        const int m = wrp * 16 + (lane >> 2);
#pragma unroll
        for (int nn = 0; nn < 8; nn++) {
            int n = nn * 8 + 2 * (lane & 3);
            const float* a = acc + nn * 4;
            ob[(size_t)n * HWP + m]           = a[0];
            ob[(size_t)(n + 1) * HWP + m]     = a[1];
            ob[(size_t)n * HWP + m + 8]       = a[2];
            ob[(size_t)(n + 1) * HWP + m + 8] = a[3];
        }
    }
}

// ---------------------------------------------------------------------------
extern "C" void kernel_launch(void* const* d_in, const int* in_sizes, int n_in,
                              void* d_out, int out_size)
{
    const float* x      = (const float*)d_in[0];
    const float* w_conv = (const float*)d_in[1];
    const float* w_off  = (const float*)d_in[2];
    const float* w_msk  = (const float*)d_in[3];

    static bool attr_set = false;
    if (!attr_set) {
        cudaFuncSetAttribute(deform_kernel,
                             cudaFuncAttributeMaxDynamicSharedMemorySize,
                             SMEM_BYTES);
        cudaFuncSetAttribute(offmask_kernel,
                             cudaFuncAttributeMaxDynamicSharedMemorySize,
                             OM_SMEM);
        attr_set = true;
    }

    nhwc_kernel<<<dim3(HWP / 32, CC / 32, BB), dim3(32, 8)>>>(x);
    frag_kernel<<<(WFRAG_N + OFRAG_N + 255) / 256, 256>>>(w_conv, w_off, w_msk);
    offmask_kernel<<<dim3(HH, BB), 128, OM_SMEM>>>();
    deform_kernel<<<dim3(HH, BB), 256, SMEM_BYTES>>>((float*)d_out);
}